// round 1
// baseline (speedup 1.0000x reference)
#include <cuda_runtime.h>

// GraphSAGE, 4 layers, dense adjacency. N=8192, F: 256 -> 128 -> 128 -> 64.
//
// Per layer: out = act( h @ W_self + adj @ (h @ W_neigh) + b )
// (projection pushed inside the aggregation via associativity: cuts the
//  8192x8192-K GEMM width from Fin to Fout).
//
// Round 0: fp32 SIMT tiled GEMM (BM=64, BN=Fout, BK=16, 4x8 reg tile,
// register-prefetch double buffering). tcgen05 path comes later.

static constexpr int MROWS = 8192;

// Scratch (device globals: no allocation allowed in kernel_launch).
__device__ float g_z [8192 * 128];   // h @ W_neigh
__device__ float g_y [8192 * 128];   // h @ W_self + b
__device__ float g_h1[8192 * 128];
__device__ float g_h2[8192 * 128];

// D[M, BN] = act( A[M, K] @ B[K, BN] (+ Cadd[M, BN]) (+ bias[BN]) )
// ldb == BN always (W slices and z buffers are row-major with row length BN).
template <int BN, int NT, bool RELU, bool ADDC, bool BIAS>
__global__ __launch_bounds__(NT) void gemm_k(
    const float* __restrict__ A, int lda,
    const float* __restrict__ B,
    const float* __restrict__ Cadd,
    const float* __restrict__ bias,
    float* __restrict__ D, int K)
{
    constexpr int BM = 64, BK = 16, TM = 4, TN = 8;
    constexpr int AF4 = (BM * BK / 4) / NT;   // float4 loads of A per thread
    constexpr int BF4 = (BK * BN / 4) / NT;   // float4 loads of B per thread
    static_assert(AF4 >= 1 && BF4 >= 1, "tile/thread mismatch");

    __shared__ float As[BK][BM];   // A stored transposed: As[k][m]
    __shared__ float Bs[BK][BN];

    const int tid = threadIdx.x;
    const int tx  = tid % (BN / TN);          // output col group
    const int ty  = tid / (BN / TN);          // output row group (0..15)
    const int m0  = blockIdx.x * BM;

    float acc[TM][TN];
#pragma unroll
    for (int i = 0; i < TM; i++)
#pragma unroll
        for (int j = 0; j < TN; j++) acc[i][j] = 0.f;

    float4 ra[AF4], rb[BF4];
    const int nkt = K / BK;

    // ---- prefetch tile 0 into registers ----
#pragma unroll
    for (int u = 0; u < AF4; u++) {
        int id = tid + u * NT;                 // 0..255
        int row = id >> 2;                     // 0..63
        int k4  = id & 3;                      // which 4-k chunk
        ra[u] = *reinterpret_cast<const float4*>(
            A + (size_t)(m0 + row) * lda + (size_t)k4 * 4);
    }
#pragma unroll
    for (int u = 0; u < BF4; u++) {
        int id  = tid + u * NT;
        int row = id / (BN / 4);               // 0..15
        int c4  = id % (BN / 4);
        rb[u] = *reinterpret_cast<const float4*>(
            B + (size_t)row * BN + (size_t)c4 * 4);
    }

    for (int kt = 0; kt < nkt; ++kt) {
        // ---- commit prefetched tile to smem ----
#pragma unroll
        for (int u = 0; u < AF4; u++) {
            int id = tid + u * NT;
            int row = id >> 2;
            int k4  = id & 3;
            As[k4 * 4 + 0][row] = ra[u].x;
            As[k4 * 4 + 1][row] = ra[u].y;
            As[k4 * 4 + 2][row] = ra[u].z;
            As[k4 * 4 + 3][row] = ra[u].w;
        }
#pragma unroll
        for (int u = 0; u < BF4; u++) {
            int id  = tid + u * NT;
            int row = id / (BN / 4);
            int c4  = id % (BN / 4);
            *reinterpret_cast<float4*>(&Bs[row][c4 * 4]) = rb[u];
        }
        __syncthreads();

        // ---- prefetch next tile while computing this one ----
        if (kt + 1 < nkt) {
            const int kb = (kt + 1) * BK;
#pragma unroll
            for (int u = 0; u < AF4; u++) {
                int id = tid + u * NT;
                int row = id >> 2;
                int k4  = id & 3;
                ra[u] = *reinterpret_cast<const float4*>(
                    A + (size_t)(m0 + row) * lda + (size_t)(kb + k4 * 4));
            }
#pragma unroll
            for (int u = 0; u < BF4; u++) {
                int id  = tid + u * NT;
                int row = id / (BN / 4);
                int c4  = id % (BN / 4);
                rb[u] = *reinterpret_cast<const float4*>(
                    B + (size_t)(kb + row) * BN + (size_t)c4 * 4);
            }
        }

        // ---- FFMA mainloop on the smem tile ----
#pragma unroll
        for (int k = 0; k < BK; k++) {
            float a[TM], b[TN];
            *reinterpret_cast<float4*>(a) =
                *reinterpret_cast<const float4*>(&As[k][ty * TM]);
            *reinterpret_cast<float4*>(b) =
                *reinterpret_cast<const float4*>(&Bs[k][tx * TN]);
            *reinterpret_cast<float4*>(b + 4) =
                *reinterpret_cast<const float4*>(&Bs[k][tx * TN + 4]);
#pragma unroll
            for (int i = 0; i < TM; i++)
#pragma unroll
                for (int j = 0; j < TN; j++)
                    acc[i][j] = fmaf(a[i], b[j], acc[i][j]);
        }
        __syncthreads();
    }

    // ---- epilogue: + Cadd, + bias, relu, store ----
#pragma unroll
    for (int i = 0; i < TM; i++) {
        const int row = m0 + ty * TM + i;
#pragma unroll
        for (int j = 0; j < TN; j += 4) {
            const int col = tx * TN + j;
            float4 v;
            v.x = acc[i][j + 0];
            v.y = acc[i][j + 1];
            v.z = acc[i][j + 2];
            v.w = acc[i][j + 3];
            if (ADDC) {
                float4 c = *reinterpret_cast<const float4*>(
                    Cadd + (size_t)row * BN + col);
                v.x += c.x; v.y += c.y; v.z += c.z; v.w += c.w;
            }
            if (BIAS) {
                float4 c = *reinterpret_cast<const float4*>(bias + col);
                v.x += c.x; v.y += c.y; v.z += c.z; v.w += c.w;
            }
            if (RELU) {
                v.x = fmaxf(v.x, 0.f); v.y = fmaxf(v.y, 0.f);
                v.z = fmaxf(v.z, 0.f); v.w = fmaxf(v.w, 0.f);
            }
            *reinterpret_cast<float4*>(D + (size_t)row * BN + col) = v;
        }
    }
}

extern "C" void kernel_launch(void* const* d_in, const int* in_sizes, int n_in,
                              void* d_out, int out_size)
{
    const float* x   = (const float*)d_in[0];   // [8192, 256]
    const float* adj = (const float*)d_in[1];   // [8192, 8192]
    const float* W1  = (const float*)d_in[2];   // [512, 128]
    const float* b1  = (const float*)d_in[3];
    const float* W2  = (const float*)d_in[4];   // [256, 128]
    const float* b2  = (const float*)d_in[5];
    const float* W3  = (const float*)d_in[6];   // [256, 128]
    const float* b3  = (const float*)d_in[7];
    const float* W4  = (const float*)d_in[8];   // [256, 64]
    const float* b4  = (const float*)d_in[9];
    float* out = (float*)d_out;                 // [8192, 64]

    float *z, *y, *h1, *h2;
    cudaGetSymbolAddress((void**)&z,  g_z);
    cudaGetSymbolAddress((void**)&y,  g_y);
    cudaGetSymbolAddress((void**)&h1, g_h1);
    cudaGetSymbolAddress((void**)&h2, g_h2);

    const dim3 grid(MROWS / 64);

    // Layer 1: Fin=256, Fout=128, relu
    gemm_k<128, 256, false, false, false><<<grid, 256>>>(x, 256, W1 + 256 * 128, nullptr, nullptr, z, 256);
    gemm_k<128, 256, false, false, true ><<<grid, 256>>>(x, 256, W1,             nullptr, b1,      y, 256);
    gemm_k<128, 256, true,  true,  false><<<grid, 256>>>(adj, 8192, z,           y,       nullptr, h1, 8192);

    // Layer 2: Fin=128, Fout=128, relu
    gemm_k<128, 256, false, false, false><<<grid, 256>>>(h1, 128, W2 + 128 * 128, nullptr, nullptr, z, 128);
    gemm_k<128, 256, false, false, true ><<<grid, 256>>>(h1, 128, W2,             nullptr, b2,      y, 128);
    gemm_k<128, 256, true,  true,  false><<<grid, 256>>>(adj, 8192, z,            y,       nullptr, h2, 8192);

    // Layer 3: Fin=128, Fout=128, relu
    gemm_k<128, 256, false, false, false><<<grid, 256>>>(h2, 128, W3 + 128 * 128, nullptr, nullptr, z, 128);
    gemm_k<128, 256, false, false, true ><<<grid, 256>>>(h2, 128, W3,             nullptr, b3,      y, 128);
    gemm_k<128, 256, true,  true,  false><<<grid, 256>>>(adj, 8192, z,            y,       nullptr, h1, 8192);

    // Layer 4: Fin=128, Fout=64, no relu -> d_out
    gemm_k<64, 128, false, false, false><<<grid, 128>>>(h1, 128, W4 + 128 * 64, nullptr, nullptr, z, 128);
    gemm_k<64, 128, false, false, true ><<<grid, 128>>>(h1, 128, W4,            nullptr, b4,      y, 128);
    gemm_k<64, 128, false, true,  false><<<grid, 128>>>(adj, 8192, z,           y,       nullptr, out, 8192);
}

// round 3
// speedup vs baseline: 2.6706x; 2.6706x over previous
#include <cuda_runtime.h>
#include <cuda_bf16.h>
#include <stdint.h>

// GraphSAGE, 4 layers, dense adjacency. N=8192, F: 256 -> 128 -> 128 -> 64.
// Per layer: h_out = act( h @ W_self + adj @ (h @ W_neigh) + b )
//
// Round 2: tcgen05 is PTX-gated out (harness emits compute_103, not _103a).
// Aggregation therefore uses legacy mma.sync bf16 (HMMA fallback on the tensor
// pipe) with hi/lo error-compensated split: Ah*Bh + Ah*Bl + Al*Bh in fp32 acc.

static constexpr int MROWS = 8192;

// Scratch (no allocation allowed anywhere).
__device__ float g_y [8192 * 128];            // h @ W_self + b (fp32)
__device__ float g_h1[8192 * 128];
__device__ float g_h2[8192 * 128];
__device__ __nv_bfloat16 g_zh[8192 * 128];    // (h @ W_neigh) hi, row-major
__device__ __nv_bfloat16 g_zl[8192 * 128];    // (h @ W_neigh) lo, row-major

// ───────────────────────── helpers ─────────────────────────
__device__ __forceinline__ uint32_t smem_u32(const void* p) {
    uint32_t a;
    asm("{ .reg .u64 t; cvta.to.shared.u64 t, %1; cvt.u32.u64 %0, t; }"
        : "=r"(a) : "l"(p));
    return a;
}
__device__ __forceinline__ uint32_t pack_hi2(float a, float b, float& ra, float& rb) {
    __nv_bfloat16 ha = __float2bfloat16(a), hb = __float2bfloat16(b);
    ra = a - __bfloat162float(ha);
    rb = b - __bfloat162float(hb);
    __nv_bfloat162 t(ha, hb);
    return *reinterpret_cast<uint32_t*>(&t);
}
__device__ __forceinline__ uint32_t pack2(float a, float b) {
    __nv_bfloat162 t(__float2bfloat16(a), __float2bfloat16(b));
    return *reinterpret_cast<uint32_t*>(&t);
}
__device__ __forceinline__ void ldsm_x4(uint32_t* r, uint32_t addr) {
    asm volatile("ldmatrix.sync.aligned.m8n8.x4.shared.b16 {%0,%1,%2,%3}, [%4];"
                 : "=r"(r[0]), "=r"(r[1]), "=r"(r[2]), "=r"(r[3]) : "r"(addr));
}
__device__ __forceinline__ void ldsm_x4_t(uint32_t* r, uint32_t addr) {
    asm volatile("ldmatrix.sync.aligned.m8n8.x4.trans.shared.b16 {%0,%1,%2,%3}, [%4];"
                 : "=r"(r[0]), "=r"(r[1]), "=r"(r[2]), "=r"(r[3]) : "r"(addr));
}
__device__ __forceinline__ void mma_bf16(float* d, const uint32_t* a,
                                         uint32_t b0, uint32_t b1) {
    asm volatile(
        "mma.sync.aligned.m16n8k16.row.col.f32.bf16.bf16.f32 "
        "{%0,%1,%2,%3}, {%4,%5,%6,%7}, {%8,%9}, {%0,%1,%2,%3};"
        : "+f"(d[0]), "+f"(d[1]), "+f"(d[2]), "+f"(d[3])
        : "r"(a[0]), "r"(a[1]), "r"(a[2]), "r"(a[3]), "r"(b0), "r"(b1));
}

// ───────────── aggregation: out = act(adj @ z + y), mma.sync bf16 split ─────────────
// adj fp32 [8192,8192]; zh/zl bf16 [8192,BN] row-major; y fp32 [8192,BN].
template <int BN>
__global__ __launch_bounds__(256) void agg_k(
    const float* __restrict__ adj,
    const __nv_bfloat16* __restrict__ zh,
    const __nv_bfloat16* __restrict__ zl,
    const float* __restrict__ y,
    float* __restrict__ out,
    int relu)
{
    constexpr int BM = 64, BK = 32, NCH = MROWS / BK;      // 256 chunks
    constexpr int LDA = 80;                                 // A smem stride (bytes)
    constexpr int LDB = BN * 2 + 16;                        // B smem stride (bytes)
    constexpr int ASZ = BM * LDA;                           // 5120 per hi/lo tile
    constexpr int BSZ = BK * LDB;
    constexpr int SSZ = 2 * ASZ + 2 * BSZ;                  // per stage
    constexpr int NTN = BN / 32;                            // n8-tiles per warp: 4 / 2
    constexpr int CW  = BN / 4;                             // warp column width
    constexpr int BQ  = (BK * BN / 8) / 256;                // uint4 B loads/thread
    constexpr int BW  = BN / 8;                             // uint4 per B row

    extern __shared__ __align__(128) char sm[];
    const uint32_t smb = smem_u32(sm);
    const int tid = threadIdx.x;
    const int m0 = blockIdx.x * BM;
    const int w = tid >> 5, lane = tid & 31;
    const int wr = w >> 2, wc = w & 3;

    float acc[2][NTN][4];
#pragma unroll
    for (int mt = 0; mt < 2; mt++)
#pragma unroll
        for (int nt = 0; nt < NTN; nt++)
#pragma unroll
            for (int q = 0; q < 4; q++) acc[mt][nt][q] = 0.f;

    float4 ra[2];
    uint4 rbh[BQ], rbl[BQ];

    auto prefetch = [&](int chunk) {
        const size_t kb = (size_t)chunk * BK;
#pragma unroll
        for (int u = 0; u < 2; u++) {
            int id = tid + u * 256, row = id >> 3, c4 = id & 7;
            ra[u] = *reinterpret_cast<const float4*>(
                adj + (size_t)(m0 + row) * MROWS + kb + c4 * 4);
        }
#pragma unroll
        for (int u = 0; u < BQ; u++) {
            int id = tid + u * 256, row = id / BW, c = id % BW;
            size_t e = (kb + row) * BN + c * 8;
            rbh[u] = *reinterpret_cast<const uint4*>(zh + e);
            rbl[u] = *reinterpret_cast<const uint4*>(zl + e);
        }
    };
    auto commit = [&](int s) {
        const int base = s * SSZ;
#pragma unroll
        for (int u = 0; u < 2; u++) {
            int id = tid + u * 256, row = id >> 3, c4 = id & 7;
            float r0, r1, r2, r3;
            uint32_t h01 = pack_hi2(ra[u].x, ra[u].y, r0, r1);
            uint32_t h23 = pack_hi2(ra[u].z, ra[u].w, r2, r3);
            int off = row * LDA + c4 * 8;
            *reinterpret_cast<uint2*>(sm + base + off) = make_uint2(h01, h23);
            *reinterpret_cast<uint2*>(sm + base + ASZ + off) =
                make_uint2(pack2(r0, r1), pack2(r2, r3));
        }
#pragma unroll
        for (int u = 0; u < BQ; u++) {
            int id = tid + u * 256, row = id / BW, c = id % BW;
            int off = row * LDB + c * 16;
            *reinterpret_cast<uint4*>(sm + base + 2 * ASZ + off) = rbh[u];
            *reinterpret_cast<uint4*>(sm + base + 2 * ASZ + BSZ + off) = rbl[u];
        }
    };
    auto compute = [&](int s) {
        const uint32_t sb = smb + s * SSZ;
#pragma unroll
        for (int ks = 0; ks < 2; ks++) {
            uint32_t ah[2][4], al[2][4];
#pragma unroll
            for (int mt = 0; mt < 2; mt++) {
                int row = wr * 32 + mt * 16 + (lane & 15);
                uint32_t ao = sb + row * LDA + ks * 32 + (lane >> 4) * 16;
                ldsm_x4(ah[mt], ao);
                ldsm_x4(al[mt], ao + ASZ);
            }
            uint32_t bh[NTN / 2][4], bl[NTN / 2][4];
#pragma unroll
            for (int bt = 0; bt < NTN / 2; bt++) {
                int krow = ks * 16 + (lane & 15);
                int ncol = wc * CW + bt * 16 + (lane >> 4) * 8;
                uint32_t bo = sb + 2 * ASZ + krow * LDB + ncol * 2;
                ldsm_x4_t(bh[bt], bo);
                ldsm_x4_t(bl[bt], bo + BSZ);
            }
#pragma unroll
            for (int mt = 0; mt < 2; mt++)
#pragma unroll
                for (int nt = 0; nt < NTN; nt++) {
                    const int bs = nt >> 1, p = (nt & 1) * 2;
                    mma_bf16(acc[mt][nt], ah[mt], bh[bs][p], bh[bs][p + 1]);
                    mma_bf16(acc[mt][nt], ah[mt], bl[bs][p], bl[bs][p + 1]);
                    mma_bf16(acc[mt][nt], al[mt], bh[bs][p], bh[bs][p + 1]);
                }
        }
    };

    prefetch(0);
    for (int i = 0; i < NCH; i++) {
        const int s = i & 1;
        commit(s);
        __syncthreads();
        if (i + 1 < NCH) prefetch(i + 1);
        compute(s);
        // no trailing sync: next iteration writes the other stage; the single
        // barrier above separates every commit(stage) from the prior reads.
    }

    // epilogue: + y, relu, store fp32
    const int g = lane >> 2, cp = (lane & 3) * 2;
#pragma unroll
    for (int mt = 0; mt < 2; mt++) {
        const int r0 = m0 + wr * 32 + mt * 16 + g;
#pragma unroll
        for (int nt = 0; nt < NTN; nt++) {
            const int col = wc * CW + nt * 8 + cp;
#pragma unroll
            for (int half = 0; half < 2; half++) {
                const size_t row = (size_t)(r0 + half * 8);
                float2 yv = *reinterpret_cast<const float2*>(y + row * BN + col);
                float v0 = acc[mt][nt][2 * half + 0] + yv.x;
                float v1 = acc[mt][nt][2 * half + 1] + yv.y;
                if (relu) { v0 = fmaxf(v0, 0.f); v1 = fmaxf(v1, 0.f); }
                *reinterpret_cast<float2*>(out + row * BN + col) =
                    make_float2(v0, v1);
            }
        }
    }
}

// ───────────── SIMT fp32 projection GEMM (small K) ─────────────
// D[M,BN] = A[M,K] @ B[K,BN] (+bias), or (ZOUT) write bf16 hi/lo row-major.
template <int BN, int NT, bool BIAS, bool ZOUT>
__global__ __launch_bounds__(NT) void gemm_k(
    const float* __restrict__ A, int lda,
    const float* __restrict__ B,
    const float* __restrict__ bias,
    float* __restrict__ D,
    __nv_bfloat16* __restrict__ zh,
    __nv_bfloat16* __restrict__ zl,
    int K)
{
    constexpr int BM = 64, BK = 16, TM = 4, TN = 8;
    constexpr int AF4 = (BM * BK / 4) / NT;
    constexpr int BF4 = (BK * BN / 4) / NT;

    __shared__ float As[BK][BM];
    __shared__ float Bs[BK][BN];

    const int tid = threadIdx.x;
    const int tx = tid % (BN / TN);
    const int ty = tid / (BN / TN);
    const int m0 = blockIdx.x * BM;

    float acc[TM][TN];
#pragma unroll
    for (int i = 0; i < TM; i++)
#pragma unroll
        for (int j = 0; j < TN; j++) acc[i][j] = 0.f;

    float4 ra[AF4], rb[BF4];
    const int nkt = K / BK;

#pragma unroll
    for (int u = 0; u < AF4; u++) {
        int id = tid + u * NT, row = id >> 2, k4 = id & 3;
        ra[u] = *reinterpret_cast<const float4*>(A + (size_t)(m0 + row) * lda + k4 * 4);
    }
#pragma unroll
    for (int u = 0; u < BF4; u++) {
        int id = tid + u * NT, row = id / (BN / 4), c4 = id % (BN / 4);
        rb[u] = *reinterpret_cast<const float4*>(B + (size_t)row * BN + c4 * 4);
    }

    for (int kt = 0; kt < nkt; ++kt) {
#pragma unroll
        for (int u = 0; u < AF4; u++) {
            int id = tid + u * NT, row = id >> 2, k4 = id & 3;
            As[k4 * 4 + 0][row] = ra[u].x;
            As[k4 * 4 + 1][row] = ra[u].y;
            As[k4 * 4 + 2][row] = ra[u].z;
            As[k4 * 4 + 3][row] = ra[u].w;
        }
#pragma unroll
        for (int u = 0; u < BF4; u++) {
            int id = tid + u * NT, row = id / (BN / 4), c4 = id % (BN / 4);
            *reinterpret_cast<float4*>(&Bs[row][c4 * 4]) = rb[u];
        }
        __syncthreads();
        if (kt + 1 < nkt) {
            const int kb = (kt + 1) * BK;
#pragma unroll
            for (int u = 0; u < AF4; u++) {
                int id = tid + u * NT, row = id >> 2, k4 = id & 3;
                ra[u] = *reinterpret_cast<const float4*>(
                    A + (size_t)(m0 + row) * lda + kb + k4 * 4);
            }
#pragma unroll
            for (int u = 0; u < BF4; u++) {
                int id = tid + u * NT, row = id / (BN / 4), c4 = id % (BN / 4);
                rb[u] = *reinterpret_cast<const float4*>(
                    B + (size_t)(kb + row) * BN + c4 * 4);
            }
        }
#pragma unroll
        for (int k = 0; k < BK; k++) {
            float a[TM], b[TN];
            *reinterpret_cast<float4*>(a) =
                *reinterpret_cast<const float4*>(&As[k][ty * TM]);
            *reinterpret_cast<float4*>(b) =
                *reinterpret_cast<const float4*>(&Bs[k][tx * TN]);
            *reinterpret_cast<float4*>(b + 4) =
                *reinterpret_cast<const float4*>(&Bs[k][tx * TN + 4]);
#pragma unroll
            for (int i = 0; i < TM; i++)
#pragma unroll
                for (int j = 0; j < TN; j++)
                    acc[i][j] = fmaf(a[i], b[j], acc[i][j]);
        }
        __syncthreads();
    }

#pragma unroll
    for (int i = 0; i < TM; i++) {
        const int row = m0 + ty * TM + i;
        if (ZOUT) {
#pragma unroll
            for (int j = 0; j < TN; j += 2) {
                const int col = tx * TN + j;
                float r0, r1;
                uint32_t h = pack_hi2(acc[i][j], acc[i][j + 1], r0, r1);
                *reinterpret_cast<uint32_t*>(zh + (size_t)row * BN + col) = h;
                *reinterpret_cast<uint32_t*>(zl + (size_t)row * BN + col) = pack2(r0, r1);
            }
        } else {
#pragma unroll
            for (int j = 0; j < TN; j += 4) {
                const int col = tx * TN + j;
                float4 v = make_float4(acc[i][j], acc[i][j + 1],
                                       acc[i][j + 2], acc[i][j + 3]);
                if (BIAS) {
                    float4 c = *reinterpret_cast<const float4*>(bias + col);
                    v.x += c.x; v.y += c.y; v.z += c.z; v.w += c.w;
                }
                *reinterpret_cast<float4*>(D + (size_t)row * BN + col) = v;
            }
        }
    }
}

// ───────────────────────────── launch ─────────────────────────────
extern "C" void kernel_launch(void* const* d_in, const int* in_sizes, int n_in,
                              void* d_out, int out_size)
{
    const float* x   = (const float*)d_in[0];
    const float* adj = (const float*)d_in[1];
    const float* W1  = (const float*)d_in[2];
    const float* b1  = (const float*)d_in[3];
    const float* W2  = (const float*)d_in[4];
    const float* b2  = (const float*)d_in[5];
    const float* W3  = (const float*)d_in[6];
    const float* b3  = (const float*)d_in[7];
    const float* W4  = (const float*)d_in[8];
    const float* b4  = (const float*)d_in[9];
    float* out = (float*)d_out;

    float *y, *h1, *h2;
    __nv_bfloat16 *zh, *zl;
    cudaGetSymbolAddress((void**)&y,  g_y);
    cudaGetSymbolAddress((void**)&h1, g_h1);
    cudaGetSymbolAddress((void**)&h2, g_h2);
    cudaGetSymbolAddress((void**)&zh, g_zh);
    cudaGetSymbolAddress((void**)&zl, g_zl);

    // dynamic smem: 2 stages of (2*A + 2*B) tiles
    constexpr int SM128 = 2 * (2 * 64 * 80 + 2 * 32 * (128 * 2 + 16));  // 55296
    constexpr int SM64  = 2 * (2 * 64 * 80 + 2 * 32 * (64 * 2 + 16));   // 38912
    cudaFuncSetAttribute(agg_k<128>, cudaFuncAttributeMaxDynamicSharedMemorySize, SM128);
    cudaFuncSetAttribute(agg_k<64>,  cudaFuncAttributeMaxDynamicSharedMemorySize, SM64);

    const dim3 pgrid(MROWS / 64);
    const dim3 agrid(MROWS / 64);

    // Layer 1 (256 -> 128, relu)
    gemm_k<128, 256, false, true ><<<pgrid, 256>>>(x, 256, W1 + 256 * 128, nullptr, nullptr, zh, zl, 256);
    gemm_k<128, 256, true,  false><<<pgrid, 256>>>(x, 256, W1, b1, y, nullptr, nullptr, 256);
    agg_k<128><<<agrid, 256, SM128>>>(adj, zh, zl, y, h1, 1);

    // Layer 2 (128 -> 128, relu)
    gemm_k<128, 256, false, true ><<<pgrid, 256>>>(h1, 128, W2 + 128 * 128, nullptr, nullptr, zh, zl, 128);
    gemm_k<128, 256, true,  false><<<pgrid, 256>>>(h1, 128, W2, b2, y, nullptr, nullptr, 128);
    agg_k<128><<<agrid, 256, SM128>>>(adj, zh, zl, y, h2, 1);

    // Layer 3 (128 -> 128, relu)
    gemm_k<128, 256, false, true ><<<pgrid, 256>>>(h2, 128, W3 + 128 * 128, nullptr, nullptr, zh, zl, 128);
    gemm_k<128, 256, true,  false><<<pgrid, 256>>>(h2, 128, W3, b3, y, nullptr, nullptr, 128);
    agg_k<128><<<agrid, 256, SM128>>>(adj, zh, zl, y, h1, 1);

    // Layer 4 (128 -> 64, no relu) -> d_out
    gemm_k<64, 128, false, true ><<<pgrid, 128>>>(h1, 128, W4 + 128 * 64, nullptr, nullptr, zh, zl, 128);
    gemm_k<64, 128, true,  false><<<pgrid, 128>>>(h1, 128, W4, b4, y, nullptr, nullptr, 128);
    agg_k<64><<<agrid, 256, SM64>>>(adj, zh, zl, y, out, 0);
}